// round 8
// baseline (speedup 1.0000x reference)
#include <cuda_runtime.h>
#include <cuda_bf16.h>
#include <cstdint>

#define IMG_H 480
#define IMG_W 640
#define IMG_HW (IMG_H * IMG_W)
#define OCH 64
#define KK 25
#define TKX 128          // CTA tile width (px)
#define TKY 2            // CTA tile rows
#define SW 132           // halo row width
#define SH 6             // halo rows
#define THREADS 256
#define PXC 256          // pixels per CTA
#define PXS 264          // padded px stride (u32) for t arrays -> conflict-free frag LDS
#define WS 26            // staged weight row stride (f32)
#define THRESH 1e-4f

__device__ __forceinline__ uint32_t bf16x2_of(float lo, float hi) {
    uint32_t r;
    asm("cvt.rn.bf16x2.f32 %0, %1, %2;" : "=r"(r) : "f"(hi), "f"(lo));  // first src = high half
    return r;
}
__device__ __forceinline__ void mma16816(float* d, const uint32_t* a, const uint32_t* b) {
    asm volatile(
        "mma.sync.aligned.m16n8k16.row.col.f32.bf16.bf16.f32 "
        "{%0,%1,%2,%3}, {%4,%5,%6,%7}, {%8,%9}, {%0,%1,%2,%3};"
        : "+f"(d[0]), "+f"(d[1]), "+f"(d[2]), "+f"(d[3])
        : "r"(a[0]), "r"(a[1]), "r"(a[2]), "r"(a[3]), "r"(b[0]), "r"(b[1]));
}

__global__ __launch_bounds__(THREADS, 2)
void normdepthconv_mma_kernel(const float* __restrict__ x,
                              const float* __restrict__ wt,
                              float* __restrict__ out) {
    __shared__ float    tile[SH * SW];        // 3168 B halo
    __shared__ float    wsm[OCH * WS];        // 6656 B staged weights
    __shared__ uint32_t tsh[16 * PXS];        // 16896 B  th bf16x2 k-pairs [kp][px]
    __shared__ uint32_t tsl[16 * PXS];        // 16896 B  tl bf16x2 k-pairs

    const int b   = blockIdx.z;
    const int X0  = blockIdx.x * TKX;
    const int Y0  = blockIdx.y * TKY;
    const int tid = threadIdx.x;

    // ---- stage halo tile (zero-padded) + raw weights ----
    const float* xb = x + (size_t)b * IMG_HW;
    for (int i = tid; i < SH * SW; i += THREADS) {
        int r = i / SW, c = i - r * SW;
        int gy = Y0 - 2 + r, gx = X0 - 2 + c;
        float v = 0.f;
        if (gy >= 0 && gy < IMG_H && gx >= 0 && gx < IMG_W) v = xb[gy * IMG_W + gx];
        tile[i] = v;
    }
    for (int i = tid; i < OCH * KK; i += THREADS) {
        int o = i / KK, k = i - o * KK;
        wsm[o * WS + k] = wt[i];
    }
    __syncthreads();

    // ---- t generation: 1 px/thread, f32 exact, then bf16 split to smem ----
    {
        const int p  = tid;
        const int ty = p >> 7;
        const int xx = p & 127;
        float v[KK];
#pragma unroll
        for (int dy = 0; dy < 5; ++dy)
#pragma unroll
            for (int i = 0; i < 5; ++i)
                v[dy * 5 + i] = tile[(ty + dy) * SW + xx + i];
        float S = 0.f, Nv = 0.f;
#pragma unroll
        for (int k = 0; k < KK; ++k) {
            S += v[k];
            Nv += (v[k] > THRESH) ? 1.f : 0.f;
        }
        const float ref = S / (Nv + 1e-6f);
#pragma unroll
        for (int k = 0; k < KK; ++k)
            v[k] = (v[k] > THRESH) ? (ref - v[k]) : 0.f;
#pragma unroll
        for (int j = 0; j < 16; ++j) {
            float a  = (2 * j     < KK) ? v[2 * j]     : 0.f;
            float bb = (2 * j + 1 < KK) ? v[2 * j + 1] : 0.f;
            uint32_t h = bf16x2_of(a, bb);
            float ha = __uint_as_float(h << 16);
            float hb = __uint_as_float(h & 0xffff0000u);
            tsh[j * PXS + p] = h;
            tsl[j * PXS + p] = bf16x2_of(a - ha, bb - hb);
        }
    }

    // ---- W fragments (resident, built once): Wh/Wl per m-tile & k-step ----
    const int lane = tid & 31;
    const int g    = lane >> 2;     // group id (fragment row sel)
    const int tig  = lane & 3;      // thread-in-group (fragment col sel)

    uint32_t WhA[4][2][4], WlA[4][2][4];
#pragma unroll
    for (int mt = 0; mt < 4; ++mt) {
#pragma unroll
        for (int s = 0; s < 2; ++s) {
#pragma unroll
            for (int r = 0; r < 4; ++r) {
                // a0:(g,kpA) a1:(g+8,kpA) a2:(g,kpA+4) a3:(g+8,kpA+4)
                int ch = mt * 16 + g + ((r & 1) ? 8 : 0);
                int kp = 8 * s + tig + ((r >> 1) ? 4 : 0);
                int k0 = 2 * kp, k1 = k0 + 1;
                float w0 = (k0 < KK) ? wsm[ch * WS + k0] : 0.f;
                float w1 = (k1 < KK) ? wsm[ch * WS + k1] : 0.f;
                uint32_t h = bf16x2_of(w0, w1);
                float h0 = __uint_as_float(h << 16);
                float h1 = __uint_as_float(h & 0xffff0000u);
                WhA[mt][s][r] = h;
                WlA[mt][s][r] = bf16x2_of(w0 - h0, w1 - h1);
            }
        }
    }
    __syncthreads();

    // ---- GEMM: D[64ch x 8px] tiles via HMMA, warp covers 32 px ----
    const int warp = tid >> 5;
    float* outb = out + (size_t)b * OCH * IMG_HW;

#pragma unroll
    for (int nc = 0; nc < 4; ++nc) {
        const int n0  = warp * 32 + nc * 8;
        const int col = n0 + g;

        uint32_t bth[2][2], btl[2][2];
#pragma unroll
        for (int s = 0; s < 2; ++s) {
            bth[s][0] = tsh[(8 * s + tig)     * PXS + col];
            bth[s][1] = tsh[(8 * s + tig + 4) * PXS + col];
            btl[s][0] = tsl[(8 * s + tig)     * PXS + col];
            btl[s][1] = tsl[(8 * s + tig + 4) * PXS + col];
        }

        float acc[4][4];
#pragma unroll
        for (int mt = 0; mt < 4; ++mt)
#pragma unroll
            for (int r = 0; r < 4; ++r) acc[mt][r] = 0.f;

#pragma unroll
        for (int mt = 0; mt < 4; ++mt) {
#pragma unroll
            for (int s = 0; s < 2; ++s) mma16816(acc[mt], WhA[mt][s], bth[s]);
#pragma unroll
            for (int s = 0; s < 2; ++s) mma16816(acc[mt], WhA[mt][s], btl[s]);
#pragma unroll
            for (int s = 0; s < 2; ++s) mma16816(acc[mt], WlA[mt][s], bth[s]);
        }

        // ---- store: lane owns adjacent px pair (p0, p0+1) per channel ----
        const int p0  = n0 + 2 * tig;
        const int row = p0 >> 7;
        const int xo  = p0 & 127;
        float* base = outb + (size_t)(Y0 + row) * IMG_W + (X0 + xo);
#pragma unroll
        for (int mt = 0; mt < 4; ++mt) {
            const int ch = mt * 16 + g;
            *reinterpret_cast<float2*>(base + (size_t)ch * IMG_HW) =
                make_float2(acc[mt][0], acc[mt][1]);
            *reinterpret_cast<float2*>(base + (size_t)(ch + 8) * IMG_HW) =
                make_float2(acc[mt][2], acc[mt][3]);
        }
    }
}

extern "C" void kernel_launch(void* const* d_in, const int* in_sizes, int n_in,
                              void* d_out, int out_size) {
    const float* x = (const float*)d_in[0];
    const float* w = (const float*)d_in[1];
    if (n_in >= 2 && in_sizes[0] == OCH * KK) {   // defensive input-order check
        x = (const float*)d_in[1];
        w = (const float*)d_in[0];
    }
    dim3 grid(IMG_W / TKX, IMG_H / TKY, 8);   // 5 x 240 x 8 = 9600 CTAs
    normdepthconv_mma_kernel<<<grid, THREADS>>>(x, w, (float*)d_out);
}

// round 10
// speedup vs baseline: 1.7526x; 1.7526x over previous
#include <cuda_runtime.h>
#include <cuda_bf16.h>
#include <cstdint>

#define IMG_H 480
#define IMG_W 640
#define IMG_HW (IMG_H * IMG_W)
#define OCH 64
#define KK 25
#define TKX 128          // CTA tile width (px)
#define TKY 2            // CTA tile rows
#define SW 132           // halo row width
#define SH 6             // halo rows
#define THREADS 128
#define PXC 256          // pixels per CTA
#define PXS 264          // padded px stride (u32) -> conflict-free frag LDS
#define THRESH 1e-4f

// fragment-ordered split weights, built once by prep kernel:
// index = lane*64 + term*32 + mt*8 + s*4 + r   (term 0=Wh, 1=Wl)
__device__ uint32_t g_wfrag[2048];

__device__ __forceinline__ uint32_t bf16x2_of(float lo, float hi) {
    uint32_t r;
    asm("cvt.rn.bf16x2.f32 %0, %1, %2;" : "=r"(r) : "f"(hi), "f"(lo));  // first src = high half
    return r;
}
__device__ __forceinline__ void mma16816(float* d, const uint32_t* a, const uint32_t* b) {
    asm volatile(
        "mma.sync.aligned.m16n8k16.row.col.f32.bf16.bf16.f32 "
        "{%0,%1,%2,%3}, {%4,%5,%6,%7}, {%8,%9}, {%0,%1,%2,%3};"
        : "+f"(d[0]), "+f"(d[1]), "+f"(d[2]), "+f"(d[3])
        : "r"(a[0]), "r"(a[1]), "r"(a[2]), "r"(a[3]), "r"(b[0]), "r"(b[1]));
}

__global__ void prep_wfrag(const float* __restrict__ wt) {
    int i = blockIdx.x * blockDim.x + threadIdx.x;   // 0..2047
    if (i >= 2048) return;
    int r    = i & 3;
    int s    = (i >> 2) & 1;
    int mt   = (i >> 3) & 3;
    int term = (i >> 5) & 1;
    int lane = i >> 6;
    int g = lane >> 2, tig = lane & 3;
    int ch = mt * 16 + g + ((r & 1) ? 8 : 0);
    int kp = 8 * s + tig + ((r >> 1) ? 4 : 0);
    int k0 = 2 * kp, k1 = k0 + 1;
    float w0 = (k0 < KK) ? wt[ch * KK + k0] : 0.f;
    float w1 = (k1 < KK) ? wt[ch * KK + k1] : 0.f;
    uint32_t h = bf16x2_of(w0, w1);
    uint32_t v = h;
    if (term) {
        float h0 = __uint_as_float(h << 16);
        float h1 = __uint_as_float(h & 0xffff0000u);
        v = bf16x2_of(w0 - h0, w1 - h1);
    }
    g_wfrag[i] = v;
}

__global__ __launch_bounds__(THREADS, 4)
void normdepthconv_mma_kernel(const float* __restrict__ x,
                              float* __restrict__ out) {
    __shared__ float    tile[SH * SW];        // 3168 B halo
    __shared__ uint32_t tsh[16 * PXS];        // 16896 B  th bf16x2 k-pairs [kp][px]
    __shared__ uint32_t tsl[16 * PXS];        // 16896 B  tl bf16x2 k-pairs

    const int b   = blockIdx.z;
    const int X0  = blockIdx.x * TKX;
    const int Y0  = blockIdx.y * TKY;
    const int tid = threadIdx.x;
    const int lane = tid & 31;
    const int warp = tid >> 5;
    const int g    = lane >> 2;     // fragment row sel
    const int tig  = lane & 3;      // fragment col sel

    // ---- W fragments: straight LDG.128 of pre-formatted data (L2-resident) ----
    uint32_t Wf[2][4][2][4];
    {
        const uint4* wp = reinterpret_cast<const uint4*>(g_wfrag + lane * 64);
#pragma unroll
        for (int q = 0; q < 16; ++q) {          // q = term*8 + mt*2 + s
            uint4 u = wp[q];
            const int term = q >> 3, mt = (q >> 1) & 3, s = q & 1;
            Wf[term][mt][s][0] = u.x;
            Wf[term][mt][s][1] = u.y;
            Wf[term][mt][s][2] = u.z;
            Wf[term][mt][s][3] = u.w;
        }
    }

    // ---- halo tile (zero-padded) ----
    const float* xb = x + (size_t)b * IMG_HW;
    for (int i = tid; i < SH * SW; i += THREADS) {
        int r = i / SW, c = i - r * SW;
        int gy = Y0 - 2 + r, gx = X0 - 2 + c;
        float v = 0.f;
        if (gy >= 0 && gy < IMG_H && gx >= 0 && gx < IMG_W) v = xb[gy * IMG_W + gx];
        tile[i] = v;
    }
    __syncthreads();

    // ---- t generation: 2 px/thread, f32 exact, bf16 split -> smem ----
#pragma unroll
    for (int half = 0; half < 2; ++half) {
        const int p  = tid + half * 128;
        const int ty = p >> 7;
        const int xx = p & 127;
        float v[KK];
#pragma unroll
        for (int dy = 0; dy < 5; ++dy)
#pragma unroll
            for (int i = 0; i < 5; ++i)
                v[dy * 5 + i] = tile[(ty + dy) * SW + xx + i];
        float S = 0.f, Nv = 0.f;
#pragma unroll
        for (int k = 0; k < KK; ++k) {
            S += v[k];
            Nv += (v[k] > THRESH) ? 1.f : 0.f;
        }
        const float ref = S / (Nv + 1e-6f);
#pragma unroll
        for (int k = 0; k < KK; ++k)
            v[k] = (v[k] > THRESH) ? (ref - v[k]) : 0.f;
#pragma unroll
        for (int j = 0; j < 16; ++j) {
            if (2 * j < KK) {
                float a  = v[2 * j];
                float bb = (2 * j + 1 < KK) ? v[2 * j + 1] : 0.f;
                uint32_t h = bf16x2_of(a, bb);
                float ha = __uint_as_float(h << 16);
                float hb = __uint_as_float(h & 0xffff0000u);
                tsh[j * PXS + p] = h;
                tsl[j * PXS + p] = bf16x2_of(a - ha, bb - hb);
            } else {
                tsh[j * PXS + p] = 0u;
                tsl[j * PXS + p] = 0u;
            }
        }
    }
    __syncthreads();

    // ---- GEMM: warp covers 64 px; D[64ch x 8px] tiles via HMMA ----
    float* outb = out + (size_t)b * OCH * IMG_HW;

#pragma unroll
    for (int nc = 0; nc < 8; ++nc) {
        const int n0  = warp * 64 + nc * 8;
        const int col = n0 + g;

        uint32_t bth[2][2], btl[2][2];
#pragma unroll
        for (int s = 0; s < 2; ++s) {
            bth[s][0] = tsh[(8 * s + tig)     * PXS + col];
            bth[s][1] = tsh[(8 * s + tig + 4) * PXS + col];
            btl[s][0] = tsl[(8 * s + tig)     * PXS + col];
            btl[s][1] = tsl[(8 * s + tig + 4) * PXS + col];
        }

        float acc[4][4];
#pragma unroll
        for (int mt = 0; mt < 4; ++mt)
#pragma unroll
            for (int r = 0; r < 4; ++r) acc[mt][r] = 0.f;

#pragma unroll
        for (int mt = 0; mt < 4; ++mt) {
#pragma unroll
            for (int s = 0; s < 2; ++s) mma16816(acc[mt], Wf[0][mt][s], bth[s]);
#pragma unroll
            for (int s = 0; s < 2; ++s) mma16816(acc[mt], Wf[0][mt][s], btl[s]);
#pragma unroll
            for (int s = 0; s < 2; ++s) mma16816(acc[mt], Wf[1][mt][s], bth[s]);
        }

        // ---- store: lane owns adjacent px pair per channel ----
        const int p0  = n0 + 2 * tig;
        const int row = p0 >> 7;
        const int xo  = p0 & 127;
        float* base = outb + (size_t)(Y0 + row) * IMG_W + (X0 + xo);
#pragma unroll
        for (int mt = 0; mt < 4; ++mt) {
            const int ch = mt * 16 + g;
            *reinterpret_cast<float2*>(base + (size_t)ch * IMG_HW) =
                make_float2(acc[mt][0], acc[mt][1]);
            *reinterpret_cast<float2*>(base + (size_t)(ch + 8) * IMG_HW) =
                make_float2(acc[mt][2], acc[mt][3]);
        }
    }
}

extern "C" void kernel_launch(void* const* d_in, const int* in_sizes, int n_in,
                              void* d_out, int out_size) {
    const float* x = (const float*)d_in[0];
    const float* w = (const float*)d_in[1];
    if (n_in >= 2 && in_sizes[0] == OCH * KK) {   // defensive input-order check
        x = (const float*)d_in[1];
        w = (const float*)d_in[0];
    }
    prep_wfrag<<<16, 128>>>(w);
    dim3 grid(IMG_W / TKX, IMG_H / TKY, 8);   // 5 x 240 x 8 = 9600 CTAs
    normdepthconv_mma_kernel<<<grid, THREADS>>>(x, (float*)d_out);
}